// round 15
// baseline (speedup 1.0000x reference)
#include <cuda_runtime.h>
#include <cstdint>

#define T_SEQ 2048
#define BATCH 256
#define HID   64
#define INP   7
#define XSTEPS 256                   // steps per prefetch block
#define XBLK_FLOATS (XSTEPS * INP)   // 1792 floats per block in GMEM
#define NBLK (T_SEQ / XSTEPS)        // 8

typedef unsigned long long ull;

__device__ __forceinline__ ull fma2(ull a, ull b, ull c) {
    ull d;
    asm("fma.rn.f32x2 %0, %1, %2, %3;" : "=l"(d) : "l"(a), "l"(b), "l"(c));
    return d;
}
__device__ __forceinline__ ull add2(ull a, ull b) {
    ull d;
    asm("add.rn.f32x2 %0, %1, %2;" : "=l"(d) : "l"(a), "l"(b));
    return d;
}
__device__ __forceinline__ ull mul2(ull a, ull b) {
    ull d;
    asm("mul.rn.f32x2 %0, %1, %2;" : "=l"(d) : "l"(a), "l"(b));
    return d;
}
__device__ __forceinline__ ull pack2(float lo, float hi) {
    ull d; asm("mov.b64 %0, {%1, %2};" : "=l"(d) : "f"(lo), "f"(hi)); return d;
}
__device__ __forceinline__ float2 unpack2(ull a) {
    float2 r; asm("mov.b64 {%0, %1}, %2;" : "=f"(r.x), "=f"(r.y) : "l"(a)); return r;
}
__device__ __forceinline__ float htanh(float x) {
    float y; asm("tanh.approx.f32 %0, %1;" : "=f"(y) : "f"(x)); return y;
}
__device__ __forceinline__ void cpa4(uint32_t dst_smem, const float* src) {
    asm volatile("cp.async.ca.shared.global [%0], [%1], 4;" :: "r"(dst_smem), "l"(src));
}
__device__ __forceinline__ void cp_commit() {
    asm volatile("cp.async.commit_group;" ::: "memory");
}
__device__ __forceinline__ void cp_wait0() {
    asm volatile("cp.async.wait_group 0;" ::: "memory");
}

// grid = 128 CTAs x 256 threads; CTA runs 2 independent batch chains
// (chain = tid>>7), 4 warps each, per-chain NAMED barriers (free-running),
// xz shadow AFTER the barrier (R12), 8 accumulators + folded activation
// scales (R14).
//
// R15 changes:
//  1. PERIODIC RE-STAGGER: chain 1 burns ~140 cyc at every ring boundary
//     (8x per run, ~0.1% total cost) to re-seed the anti-phase offset that a
//     one-time stagger loses to phase-locking. One chain's serial tail then
//     overlaps the other's FMA block throughout each 256-step span.
//  2. XSTEPS 128->256: half the boundary overhead again.
//  3. h2 = 2h: h stored as (1+tanh(zo'))*tanh(c) via a single FMA; the o/g
//     rows shuffle RAW tanh values (no affine before shfl) and the extra 0.5
//     folds exactly into the W_hh register scales and W_lin's forward half.
//
// Per chain: thread w in [0,128): p = w&1, u = w>>1, rows rA = p*64+u (i/f),
// rB = rA+128 (g/o); weights register-resident. Unified MUFU.TANH
// activations, shfl_xor(1) gate exchange, p==0 lanes update c and store h2
// (double-buffered by step parity). ONE named barrier per step.
//
// Backward direction = ONE LSTM step on x[T-1] from zero state (scan[0] of
// the reversed sequence), fused as an epilogue with the final linear.
struct ChainSmem {
    float h[2][64];             // double-buffered hidden state (holds 2h)
    float hb[64];               // backward h (epilogue, true scale)
    float xring[2][XSTEPS * 8]; // padded x ring, 2 blocks (contiguous)
    float pad[8];               // absorbs end-of-ring shadow over-read
};

__global__ void __launch_bounds__(256, 1)
bilstm_kernel(const float* __restrict__ x,      // [B,T,I]
              const float* __restrict__ Wih_f,  // [256,7]
              const float* __restrict__ Whh_f,  // [256,64]
              const float* __restrict__ bih_f,  // [256]
              const float* __restrict__ bhh_f,  // [256]
              const float* __restrict__ Wih_b,  // [256,7]
              const float* __restrict__ Whh_b,  // unused (h0 = 0 for single bwd step)
              const float* __restrict__ bih_b,  // [256]
              const float* __restrict__ bhh_b,  // [256]
              const float* __restrict__ Wlin,   // [3,128]
              const float* __restrict__ blin,   // [3]
              float* __restrict__ out)          // [B,3]
{
    __shared__ __align__(16) ChainSmem cs[2];

    const int tid   = threadIdx.x;
    const int chain = tid >> 7;          // 0 or 1
    const int w     = tid & 127;         // within-chain thread id
    const int p     = w & 1;             // gate pair selector
    const int u     = w >> 1;            // hidden unit
    const int rA    = p * 64 + u;        // gate i (p=0) / f (p=1)
    const int rB    = rA + 128;          // gate g (p=0) / o (p=1)
    const int b     = blockIdx.x * 2 + chain;
    const int barid = 1 + chain;
    ChainSmem& S = cs[chain];

    const float* xb = x + (size_t)b * T_SEQ * INP;

    const uint32_t ring0 = (uint32_t)__cvta_generic_to_shared(&S.xring[0][0]);
    const uint32_t ring1 = (uint32_t)__cvta_generic_to_shared(&S.xring[1][0]);

    // input scale of row B: 1.0 for p=0 (g: tanh(z)), 0.5 for p=1 (o: sigmoid)
    const float actB_s = (p == 0) ? 1.0f : 0.5f;

    // ---- weights into registers, activation AND h2 scales folded in ----
    // W_hh multiplies stored h2 = 2h -> extra 0.5 on the hh part only.
    // row A (i/f, sigmoid): hh scale 0.25; row B: actB_s * 0.5.
    ull wA[32], wB[32];
    {
        const ull sA2 = pack2(0.25f, 0.25f);
        const ull sB2 = pack2(actB_s * 0.5f, actB_s * 0.5f);
        const ull* a  = reinterpret_cast<const ull*>(Whh_f + rA * HID);
        const ull* c2 = reinterpret_cast<const ull*>(Whh_f + rB * HID);
#pragma unroll
        for (int m = 0; m < 32; m++) wA[m] = mul2(a[m], sA2);
#pragma unroll
        for (int m = 0; m < 32; m++) wB[m] = mul2(c2[m], sB2);
    }
    ull wihA[4], wihB[4];
    {
        float t[8];
#pragma unroll
        for (int i = 0; i < INP; i++) t[i] = 0.5f * Wih_f[rA * INP + i];
        t[7] = 0.0f;
#pragma unroll
        for (int m = 0; m < 4; m++) wihA[m] = pack2(t[2 * m], t[2 * m + 1]);
#pragma unroll
        for (int i = 0; i < INP; i++) t[i] = actB_s * Wih_f[rB * INP + i];
        t[7] = 0.0f;
#pragma unroll
        for (int m = 0; m < 4; m++) wihB[m] = pack2(t[2 * m], t[2 * m + 1]);
    }
    const ull biasA2 = pack2(0.5f   * (bih_f[rA] + bhh_f[rA]), 0.0f);
    const ull biasB2 = pack2(actB_s * (bih_f[rB] + bhh_f[rB]), 0.0f);

    // ---- init: h=0, zero ring pads, prefetch blocks 0 and 1 ----
    // thread w owns ring slots {w, w+128} of each buffer
    if (w < 64) S.h[0][w] = 0.0f;
    S.xring[0][w * 8 + 7] = 0.0f;
    S.xring[0][(w + 128) * 8 + 7] = 0.0f;
    S.xring[1][w * 8 + 7] = 0.0f;
    S.xring[1][(w + 128) * 8 + 7] = 0.0f;
#pragma unroll
    for (int k = 0; k < 7; k++) {
        cpa4(ring0 + (uint32_t)(w * 8 + k) * 4, xb + w * INP + k);
        cpa4(ring0 + (uint32_t)((w + 128) * 8 + k) * 4, xb + (w + 128) * INP + k);
    }
    cp_commit();
#pragma unroll
    for (int k = 0; k < 7; k++) {
        cpa4(ring1 + (uint32_t)(w * 8 + k) * 4, xb + XBLK_FLOATS + w * INP + k);
        cpa4(ring1 + (uint32_t)((w + 128) * 8 + k) * 4, xb + XBLK_FLOATS + (w + 128) * INP + k);
    }
    cp_commit();
    cp_wait0();
    float c = 0.0f;
    __syncthreads();

    // xz for slot 0; xnext walks the contiguous ring (buf0 then buf1)
    ull xzA0, xzA1, xzB0, xzB1;
    const float* xnext = &S.xring[0][0];
    {
        ulonglong2 xv = *reinterpret_cast<const ulonglong2*>(xnext);
        ulonglong2 xw = *reinterpret_cast<const ulonglong2*>(xnext + 4);
        xzA0 = fma2(wihA[0], xv.x, biasA2);
        xzA1 = fma2(wihA[1], xv.y, 0ull);
        xzB0 = fma2(wihB[0], xv.x, biasB2);
        xzB1 = fma2(wihB[1], xv.y, 0ull);
        xzA0 = fma2(wihA[2], xw.x, xzA0);
        xzA1 = fma2(wihA[3], xw.y, xzA1);
        xzB0 = fma2(wihB[2], xw.x, xzB0);
        xzB1 = fma2(wihB[3], xw.y, xzB1);
        xnext += 8;
    }

    for (int blk = 0; blk < NBLK; blk++) {
        if (blk) {
            cp_wait0();   // ring block committed at the previous boundary landed
            asm volatile("bar.sync %0, 128;" :: "r"(barid) : "memory");
            int nb = blk + 1;
            if (nb < NBLK) {
                uint32_t dst = (nb & 1) ? ring1 : ring0;
                const float* src = xb + (size_t)nb * XBLK_FLOATS;
#pragma unroll
                for (int k = 0; k < 7; k++) {
                    cpa4(dst + (uint32_t)(w * 8 + k) * 4, src + w * INP + k);
                    cpa4(dst + (uint32_t)((w + 128) * 8 + k) * 4, src + (w + 128) * INP + k);
                }
            }
            cp_commit();
            // recompute xz for slot t=blk*XSTEPS (the pre-boundary shadow may
            // have read unlanded data) and reset the walk
            const float* xc = &S.xring[blk & 1][0];
            ulonglong2 xv = *reinterpret_cast<const ulonglong2*>(xc);
            ulonglong2 xw = *reinterpret_cast<const ulonglong2*>(xc + 4);
            xzA0 = fma2(wihA[0], xv.x, biasA2);
            xzA1 = fma2(wihA[1], xv.y, 0ull);
            xzB0 = fma2(wihB[0], xv.x, biasB2);
            xzB1 = fma2(wihB[1], xv.y, 0ull);
            xzA0 = fma2(wihA[2], xw.x, xzA0);
            xzA1 = fma2(wihA[3], xw.y, xzA1);
            xzB0 = fma2(wihB[2], xw.x, xzB0);
            xzB1 = fma2(wihB[3], xw.y, xzB1);
            xnext = xc + 8;
        }
        // ---- re-seed the anti-phase offset (chain 1 only, ~140 cyc) ----
        if (chain == 1) {
            float d = c + 1.5f;
#pragma unroll
            for (int i = 0; i < 35; i++) d = fmaf(d, 0.9999999f, 1e-9f);
            asm volatile("" :: "f"(d));
        }

#pragma unroll 2
        for (int i = 0; i < XSTEPS; i++) {
            const int par = i & 1;       // h-buffer parity (XSTEPS even)

            // ---- z = xz + W_hh·h2 : 8 accumulators, dep depth 32 cyc ----
            ull a0 = xzA0, a1 = xzA1, a2 = 0ull, a3 = 0ull;
            ull b0 = xzB0, b1 = xzB1, b2 = 0ull, b3 = 0ull;
            const ulonglong2* h2 = reinterpret_cast<const ulonglong2*>(S.h[par]);
#pragma unroll
            for (int m = 0; m < 8; m++) {
                ulonglong2 ha  = h2[2 * m];
                ulonglong2 hbv = h2[2 * m + 1];
                a0 = fma2(wA[4 * m + 0], ha.x,  a0);
                a1 = fma2(wA[4 * m + 1], ha.y,  a1);
                b0 = fma2(wB[4 * m + 0], ha.x,  b0);
                b1 = fma2(wB[4 * m + 1], ha.y,  b1);
                a2 = fma2(wA[4 * m + 2], hbv.x, a2);
                a3 = fma2(wA[4 * m + 3], hbv.y, a3);
                b2 = fma2(wB[4 * m + 2], hbv.x, b2);
                b3 = fma2(wB[4 * m + 3], hbv.y, b3);
            }
            float2 fa = unpack2(add2(add2(a0, a2), add2(a1, a3)));
            float2 fb = unpack2(add2(add2(b0, b2), add2(b1, b3)));
            float zA = fa.x + fa.y;
            float zB = fb.x + fb.y;

            // ---- tail ----
            // row A (i/f sigmoid): full affine (needed for the c update).
            // row B: RAW tanh (g is tanh anyway; o's sigmoid affine folds
            // into the h2 FMA on the receiver side).
            float aA = fmaf(0.5f, htanh(zA), 0.5f);
            float aB = htanh(zB);
            float oA = __shfl_xor_sync(0xFFFFFFFFu, aA, 1);  // p=0 gets f
            float oB = __shfl_xor_sync(0xFFFFFFFFu, aB, 1);  // p=0 gets raw t_o
            if (p == 0) {
                c = oA * c + aA * aB;                 // c = f*c + i*g
                float tc = htanh(c);
                S.h[par ^ 1][u] = fmaf(oB, tc, tc);   // h2 = (1+t_o)*tanh(c) = 2h
            }

            // ---- barrier: arrive immediately after the h-store ----
            asm volatile("bar.sync %0, 128;" :: "r"(barid) : "memory");

            // ---- xz shadow AFTER the bar (overlaps drain/release) ----
            {
                ulonglong2 xv = *reinterpret_cast<const ulonglong2*>(xnext);
                ulonglong2 xw = *reinterpret_cast<const ulonglong2*>(xnext + 4);
                xzA0 = fma2(wihA[0], xv.x, biasA2);
                xzA1 = fma2(wihA[1], xv.y, 0ull);
                xzB0 = fma2(wihB[0], xv.x, biasB2);
                xzB1 = fma2(wihB[1], xv.y, 0ull);
                xzA0 = fma2(wihA[2], xw.x, xzA0);
                xzA1 = fma2(wihA[3], xw.y, xzA1);
                xzB0 = fma2(wihB[2], xw.x, xzB0);
                xzB1 = fma2(wihB[3], xw.y, xzB1);
                xnext += 8;
            }
        }
    }

    // ---- backward direction: ONE step on x[T-1] from zero state ----
    {
        const float* xl = &S.xring[1][(XSTEPS - 1) * 8]; // t=2047 -> buf 1, last slot
        float zbA = bih_b[rA] + bhh_b[rA];
        float zbB = bih_b[rB] + bhh_b[rB];
#pragma unroll
        for (int i = 0; i < INP; i++) {
            zbA += Wih_b[rA * INP + i] * xl[i];
            zbB += Wih_b[rB * INP + i] * xl[i];
        }
        float aA = fmaf(0.5f, htanh(0.5f * zbA), 0.5f);
        float aB = (p == 0) ? htanh(zbB)
                            : fmaf(0.5f, htanh(0.5f * zbB), 0.5f);
        float oB = __shfl_xor_sync(0xFFFFFFFFu, aB, 1);   // o (activated)
        if (p == 0) {
            S.hb[u] = oB * htanh(aA * aB);       // f*c0 == 0 ; true scale
        }
        asm volatile("bar.sync %0, 128;" :: "r"(barid) : "memory");
    }

    // ---- final linear: out[b] = W_lin @ concat(h_f, h_b) + b_lin ----
    // forward h is stored as 2h -> fold 0.5 into the forward Wlin half.
    if (w < 3) {
        float a = blin[w];
#pragma unroll 16
        for (int k = 0; k < 64; k++) a += 0.5f * Wlin[w * 128 + k] * S.h[0][k];
#pragma unroll 16
        for (int k = 0; k < 64; k++) a += Wlin[w * 128 + 64 + k] * S.hb[k];
        out[b * 3 + w] = a;
    }
}

extern "C" void kernel_launch(void* const* d_in, const int* in_sizes, int n_in,
                              void* d_out, int out_size) {
    (void)in_sizes; (void)n_in; (void)out_size;
    bilstm_kernel<<<BATCH / 2, 256>>>(
        (const float*)d_in[0],  (const float*)d_in[1], (const float*)d_in[2],
        (const float*)d_in[3],  (const float*)d_in[4], (const float*)d_in[5],
        (const float*)d_in[6],  (const float*)d_in[7], (const float*)d_in[8],
        (const float*)d_in[9],  (const float*)d_in[10], (float*)d_out);
}

// round 16
// speedup vs baseline: 1.0102x; 1.0102x over previous
#include <cuda_runtime.h>
#include <cstdint>

#define T_SEQ 2048
#define BATCH 256
#define HID   64
#define INP   7
#define XSTEPS 128                   // steps per prefetch block
#define XBLK_FLOATS (XSTEPS * INP)   // 896 floats per block in GMEM
#define NBLK (T_SEQ / XSTEPS)        // 16

typedef unsigned long long ull;

__device__ __forceinline__ ull fma2(ull a, ull b, ull c) {
    ull d;
    asm("fma.rn.f32x2 %0, %1, %2, %3;" : "=l"(d) : "l"(a), "l"(b), "l"(c));
    return d;
}
__device__ __forceinline__ ull add2(ull a, ull b) {
    ull d;
    asm("add.rn.f32x2 %0, %1, %2;" : "=l"(d) : "l"(a), "l"(b));
    return d;
}
__device__ __forceinline__ ull mul2(ull a, ull b) {
    ull d;
    asm("mul.rn.f32x2 %0, %1, %2;" : "=l"(d) : "l"(a), "l"(b));
    return d;
}
__device__ __forceinline__ ull pack2(float lo, float hi) {
    ull d; asm("mov.b64 %0, {%1, %2};" : "=l"(d) : "f"(lo), "f"(hi)); return d;
}
__device__ __forceinline__ float2 unpack2(ull a) {
    float2 r; asm("mov.b64 {%0, %1}, %2;" : "=f"(r.x), "=f"(r.y) : "l"(a)); return r;
}
__device__ __forceinline__ float htanh(float x) {
    float y; asm("tanh.approx.f32 %0, %1;" : "=f"(y) : "f"(x)); return y;
}
__device__ __forceinline__ void cpa4(uint32_t dst_smem, const float* src) {
    asm volatile("cp.async.ca.shared.global [%0], [%1], 4;" :: "r"(dst_smem), "l"(src));
}
__device__ __forceinline__ void cp_commit() {
    asm volatile("cp.async.commit_group;" ::: "memory");
}
__device__ __forceinline__ void cp_wait0() {
    asm volatile("cp.async.wait_group 0;" ::: "memory");
}

// grid = 128 CTAs x 256 threads; CTA runs 2 independent batch chains
// (chain = tid>>7), 4 warps each, per-chain NAMED barriers (free-running, NO
// stagger of any kind — every stagger experiment was neutral or harmful; the
// scheduler's natural interleave wins), xz shadow AFTER the barrier (R12),
// 8 accumulators + folded activation scales (R14), XSTEPS=128 (R14 best).
//
// R16 keeps ONE R15 idea on the R14 base — the h2 = 2h trick:
//   h stored as h2 = (1 + tanh(zo'))*tanh(c) = 2h via a single FMA.
//   Row B (g/o) shuffles the RAW tanh value (no affine before the 26-cyc
//   shuffle), and the extra 0.5 folds exactly into the W_hh register scales
//   (0.25 for row A, actB_s*0.5 for row B) and W_lin's forward half.
//
// Per chain: thread w in [0,128): p = w&1, u = w>>1, rows rA = p*64+u (i/f),
// rB = rA+128 (g/o); weights register-resident (2 x 32 f32x2). Unified
// MUFU.TANH activations, shfl_xor(1) gate exchange, p==0 lanes update c and
// store h2 (double-buffered by step parity). ONE named barrier per step.
//
// Backward direction = ONE LSTM step on x[T-1] from zero state (scan[0] of
// the reversed sequence), fused as an epilogue with the final linear.
struct ChainSmem {
    float h[2][64];             // double-buffered hidden state (holds 2h)
    float hb[64];               // backward h (epilogue, true scale)
    float xring[2][XSTEPS * 8]; // padded x ring, 2 blocks (contiguous)
    float pad[8];               // absorbs end-of-ring shadow over-read
};

__global__ void __launch_bounds__(256, 1)
bilstm_kernel(const float* __restrict__ x,      // [B,T,I]
              const float* __restrict__ Wih_f,  // [256,7]
              const float* __restrict__ Whh_f,  // [256,64]
              const float* __restrict__ bih_f,  // [256]
              const float* __restrict__ bhh_f,  // [256]
              const float* __restrict__ Wih_b,  // [256,7]
              const float* __restrict__ Whh_b,  // unused (h0 = 0 for single bwd step)
              const float* __restrict__ bih_b,  // [256]
              const float* __restrict__ bhh_b,  // [256]
              const float* __restrict__ Wlin,   // [3,128]
              const float* __restrict__ blin,   // [3]
              float* __restrict__ out)          // [B,3]
{
    __shared__ __align__(16) ChainSmem cs[2];

    const int tid   = threadIdx.x;
    const int chain = tid >> 7;          // 0 or 1
    const int w     = tid & 127;         // within-chain thread id
    const int p     = w & 1;             // gate pair selector
    const int u     = w >> 1;            // hidden unit
    const int rA    = p * 64 + u;        // gate i (p=0) / f (p=1)
    const int rB    = rA + 128;          // gate g (p=0) / o (p=1)
    const int b     = blockIdx.x * 2 + chain;
    const int barid = 1 + chain;
    ChainSmem& S = cs[chain];

    const float* xb = x + (size_t)b * T_SEQ * INP;

    const uint32_t ring0 = (uint32_t)__cvta_generic_to_shared(&S.xring[0][0]);
    const uint32_t ring1 = (uint32_t)__cvta_generic_to_shared(&S.xring[1][0]);

    // input scale of row B: 1.0 for p=0 (g: tanh(z)), 0.5 for p=1 (o: sigmoid)
    const float actB_s = (p == 0) ? 1.0f : 0.5f;

    // ---- weights into registers, activation AND h2 scales folded in ----
    // W_hh multiplies stored h2 = 2h -> extra 0.5 on the hh part only.
    // row A (i/f, sigmoid): hh scale 0.25; row B: actB_s * 0.5.
    ull wA[32], wB[32];
    {
        const ull sA2 = pack2(0.25f, 0.25f);
        const ull sB2 = pack2(actB_s * 0.5f, actB_s * 0.5f);
        const ull* a  = reinterpret_cast<const ull*>(Whh_f + rA * HID);
        const ull* c2 = reinterpret_cast<const ull*>(Whh_f + rB * HID);
#pragma unroll
        for (int m = 0; m < 32; m++) wA[m] = mul2(a[m], sA2);
#pragma unroll
        for (int m = 0; m < 32; m++) wB[m] = mul2(c2[m], sB2);
    }
    ull wihA[4], wihB[4];
    {
        float t[8];
#pragma unroll
        for (int i = 0; i < INP; i++) t[i] = 0.5f * Wih_f[rA * INP + i];
        t[7] = 0.0f;
#pragma unroll
        for (int m = 0; m < 4; m++) wihA[m] = pack2(t[2 * m], t[2 * m + 1]);
#pragma unroll
        for (int i = 0; i < INP; i++) t[i] = actB_s * Wih_f[rB * INP + i];
        t[7] = 0.0f;
#pragma unroll
        for (int m = 0; m < 4; m++) wihB[m] = pack2(t[2 * m], t[2 * m + 1]);
    }
    const ull biasA2 = pack2(0.5f   * (bih_f[rA] + bhh_f[rA]), 0.0f);
    const ull biasB2 = pack2(actB_s * (bih_f[rB] + bhh_f[rB]), 0.0f);

    // ---- init: h=0, zero ring pads, prefetch blocks 0 and 1 ----
    // thread w owns ring slot w (both buffers)
    if (w < 64) S.h[0][w] = 0.0f;
    S.xring[0][w * 8 + 7] = 0.0f;
    S.xring[1][w * 8 + 7] = 0.0f;
#pragma unroll
    for (int k = 0; k < 7; k++)
        cpa4(ring0 + (uint32_t)(w * 8 + k) * 4, xb + w * INP + k);
    cp_commit();
#pragma unroll
    for (int k = 0; k < 7; k++)
        cpa4(ring1 + (uint32_t)(w * 8 + k) * 4, xb + XBLK_FLOATS + w * INP + k);
    cp_commit();
    cp_wait0();
    float c = 0.0f;
    __syncthreads();

    // xz for slot 0; xnext walks the contiguous ring (buf0 then buf1)
    ull xzA0, xzA1, xzB0, xzB1;
    const float* xnext = &S.xring[0][0];
    {
        ulonglong2 xv = *reinterpret_cast<const ulonglong2*>(xnext);
        ulonglong2 xw = *reinterpret_cast<const ulonglong2*>(xnext + 4);
        xzA0 = fma2(wihA[0], xv.x, biasA2);
        xzA1 = fma2(wihA[1], xv.y, 0ull);
        xzB0 = fma2(wihB[0], xv.x, biasB2);
        xzB1 = fma2(wihB[1], xv.y, 0ull);
        xzA0 = fma2(wihA[2], xw.x, xzA0);
        xzA1 = fma2(wihA[3], xw.y, xzA1);
        xzB0 = fma2(wihB[2], xw.x, xzB0);
        xzB1 = fma2(wihB[3], xw.y, xzB1);
        xnext += 8;
    }

    for (int blk = 0; blk < NBLK; blk++) {
        if (blk) {
            cp_wait0();   // ring block committed at the previous boundary landed
            asm volatile("bar.sync %0, 128;" :: "r"(barid) : "memory");
            int nb = blk + 1;
            if (nb < NBLK) {
                uint32_t dst = (nb & 1) ? ring1 : ring0;
                const float* src = xb + (size_t)nb * XBLK_FLOATS + w * INP;
#pragma unroll
                for (int k = 0; k < 7; k++)
                    cpa4(dst + (uint32_t)(w * 8 + k) * 4, src + k);
            }
            cp_commit();
            // recompute xz for slot t=blk*XSTEPS (the pre-boundary shadow may
            // have read unlanded data) and reset the walk
            const float* xc = &S.xring[blk & 1][0];
            ulonglong2 xv = *reinterpret_cast<const ulonglong2*>(xc);
            ulonglong2 xw = *reinterpret_cast<const ulonglong2*>(xc + 4);
            xzA0 = fma2(wihA[0], xv.x, biasA2);
            xzA1 = fma2(wihA[1], xv.y, 0ull);
            xzB0 = fma2(wihB[0], xv.x, biasB2);
            xzB1 = fma2(wihB[1], xv.y, 0ull);
            xzA0 = fma2(wihA[2], xw.x, xzA0);
            xzA1 = fma2(wihA[3], xw.y, xzA1);
            xzB0 = fma2(wihB[2], xw.x, xzB0);
            xzB1 = fma2(wihB[3], xw.y, xzB1);
            xnext = xc + 8;
        }

#pragma unroll 2
        for (int i = 0; i < XSTEPS; i++) {
            const int par = i & 1;       // h-buffer parity (XSTEPS even)

            // ---- z = xz + W_hh·h2 : 8 accumulators, dep depth 32 cyc ----
            ull a0 = xzA0, a1 = xzA1, a2 = 0ull, a3 = 0ull;
            ull b0 = xzB0, b1 = xzB1, b2 = 0ull, b3 = 0ull;
            const ulonglong2* h2 = reinterpret_cast<const ulonglong2*>(S.h[par]);
#pragma unroll
            for (int m = 0; m < 8; m++) {
                ulonglong2 ha  = h2[2 * m];
                ulonglong2 hbv = h2[2 * m + 1];
                a0 = fma2(wA[4 * m + 0], ha.x,  a0);
                a1 = fma2(wA[4 * m + 1], ha.y,  a1);
                b0 = fma2(wB[4 * m + 0], ha.x,  b0);
                b1 = fma2(wB[4 * m + 1], ha.y,  b1);
                a2 = fma2(wA[4 * m + 2], hbv.x, a2);
                a3 = fma2(wA[4 * m + 3], hbv.y, a3);
                b2 = fma2(wB[4 * m + 2], hbv.x, b2);
                b3 = fma2(wB[4 * m + 3], hbv.y, b3);
            }
            float2 fa = unpack2(add2(add2(a0, a2), add2(a1, a3)));
            float2 fb = unpack2(add2(add2(b0, b2), add2(b1, b3)));
            float zA = fa.x + fa.y;
            float zB = fb.x + fb.y;

            // ---- tail ----
            // row A (i/f sigmoid): full affine (needed for the c update).
            // row B: RAW tanh (g is tanh anyway; o's sigmoid affine folds
            // into the receiver-side h2 FMA).
            float aA = fmaf(0.5f, htanh(zA), 0.5f);
            float aB = htanh(zB);
            float oA = __shfl_xor_sync(0xFFFFFFFFu, aA, 1);  // p=0 gets f
            float oB = __shfl_xor_sync(0xFFFFFFFFu, aB, 1);  // p=0 gets raw t_o
            if (p == 0) {
                c = oA * c + aA * aB;                 // c = f*c + i*g
                float tc = htanh(c);
                S.h[par ^ 1][u] = fmaf(oB, tc, tc);   // h2 = (1+t_o)*tanh(c) = 2h
            }

            // ---- barrier: arrive immediately after the h-store ----
            asm volatile("bar.sync %0, 128;" :: "r"(barid) : "memory");

            // ---- xz shadow AFTER the bar (overlaps drain/release) ----
            {
                ulonglong2 xv = *reinterpret_cast<const ulonglong2*>(xnext);
                ulonglong2 xw = *reinterpret_cast<const ulonglong2*>(xnext + 4);
                xzA0 = fma2(wihA[0], xv.x, biasA2);
                xzA1 = fma2(wihA[1], xv.y, 0ull);
                xzB0 = fma2(wihB[0], xv.x, biasB2);
                xzB1 = fma2(wihB[1], xv.y, 0ull);
                xzA0 = fma2(wihA[2], xw.x, xzA0);
                xzA1 = fma2(wihA[3], xw.y, xzA1);
                xzB0 = fma2(wihB[2], xw.x, xzB0);
                xzB1 = fma2(wihB[3], xw.y, xzB1);
                xnext += 8;
            }
        }
    }

    // ---- backward direction: ONE step on x[T-1] from zero state ----
    {
        const float* xl = &S.xring[1][(XSTEPS - 1) * 8]; // t=2047 -> buf 1, slot 127
        float zbA = bih_b[rA] + bhh_b[rA];
        float zbB = bih_b[rB] + bhh_b[rB];
#pragma unroll
        for (int i = 0; i < INP; i++) {
            zbA += Wih_b[rA * INP + i] * xl[i];
            zbB += Wih_b[rB * INP + i] * xl[i];
        }
        float aA = fmaf(0.5f, htanh(0.5f * zbA), 0.5f);
        float aB = (p == 0) ? htanh(zbB)
                            : fmaf(0.5f, htanh(0.5f * zbB), 0.5f);
        float oB = __shfl_xor_sync(0xFFFFFFFFu, aB, 1);   // o (activated)
        if (p == 0) {
            S.hb[u] = oB * htanh(aA * aB);       // f*c0 == 0 ; true scale
        }
        asm volatile("bar.sync %0, 128;" :: "r"(barid) : "memory");
    }

    // ---- final linear: out[b] = W_lin @ concat(h_f, h_b) + b_lin ----
    // forward h is stored as 2h -> fold 0.5 into the forward Wlin half.
    if (w < 3) {
        float a = blin[w];
#pragma unroll 16
        for (int k = 0; k < 64; k++) a += 0.5f * Wlin[w * 128 + k] * S.h[0][k];
#pragma unroll 16
        for (int k = 0; k < 64; k++) a += Wlin[w * 128 + 64 + k] * S.hb[k];
        out[b * 3 + w] = a;
    }
}

extern "C" void kernel_launch(void* const* d_in, const int* in_sizes, int n_in,
                              void* d_out, int out_size) {
    (void)in_sizes; (void)n_in; (void)out_size;
    bilstm_kernel<<<BATCH / 2, 256>>>(
        (const float*)d_in[0],  (const float*)d_in[1], (const float*)d_in[2],
        (const float*)d_in[3],  (const float*)d_in[4], (const float*)d_in[5],
        (const float*)d_in[6],  (const float*)d_in[7], (const float*)d_in[8],
        (const float*)d_in[9],  (const float*)d_in[10], (float*)d_out);
}

// round 17
// speedup vs baseline: 1.1131x; 1.1018x over previous
#include <cuda_runtime.h>
#include <cstdint>

#define T_SEQ 2048
#define BATCH 256
#define HID   64
#define INP   7
#define XSTEPS 128                   // steps per prefetch block
#define XBLK_FLOATS (XSTEPS * INP)   // 896 floats per block in GMEM
#define NBLK (T_SEQ / XSTEPS)        // 16

typedef unsigned long long ull;

__device__ __forceinline__ ull fma2(ull a, ull b, ull c) {
    ull d;
    asm("fma.rn.f32x2 %0, %1, %2, %3;" : "=l"(d) : "l"(a), "l"(b), "l"(c));
    return d;
}
__device__ __forceinline__ ull add2(ull a, ull b) {
    ull d;
    asm("add.rn.f32x2 %0, %1, %2;" : "=l"(d) : "l"(a), "l"(b));
    return d;
}
__device__ __forceinline__ ull mul2(ull a, ull b) {
    ull d;
    asm("mul.rn.f32x2 %0, %1, %2;" : "=l"(d) : "l"(a), "l"(b));
    return d;
}
__device__ __forceinline__ ull pack2(float lo, float hi) {
    ull d; asm("mov.b64 %0, {%1, %2};" : "=l"(d) : "f"(lo), "f"(hi)); return d;
}
__device__ __forceinline__ float2 unpack2(ull a) {
    float2 r; asm("mov.b64 {%0, %1}, %2;" : "=f"(r.x), "=f"(r.y) : "l"(a)); return r;
}
__device__ __forceinline__ float htanh(float x) {
    float y; asm("tanh.approx.f32 %0, %1;" : "=f"(y) : "f"(x)); return y;
}
__device__ __forceinline__ void cpa4(uint32_t dst_smem, const float* src) {
    asm volatile("cp.async.ca.shared.global [%0], [%1], 4;" :: "r"(dst_smem), "l"(src));
}
__device__ __forceinline__ void cp_commit() {
    asm volatile("cp.async.commit_group;" ::: "memory");
}
__device__ __forceinline__ void cp_wait0() {
    asm volatile("cp.async.wait_group 0;" ::: "memory");
}

// grid = 128 CTAs x 256 threads; CTA runs 2 independent batch chains
// (chain = tid>>7), 4 warps each, per-chain NAMED barriers (free-running),
// xz shadow AFTER the barrier (R12 win: overlaps the bar drain/release under
// DEFER_BLOCKING semantics).
//
// This is the exact R14 configuration — the empirical optimum of the search:
//  1. 8 accumulators (4 per gate row): dot-product dependency depth 32 cyc.
//  2. Activation scales folded into the weights at load: all sigmoid rows
//     (i, f, o) have W/Wih/bias pre-scaled by 0.5 (exact), so the tail is
//     tanh(z) directly — no multiply before MUFU.TANH on the critical path.
//  3. XSTEPS=128: thread w owns ring slot w (7 cp.async per boundary).
//  4. One-time anti-phase stagger on chain 1 (measurably part of the best).
// Rejected by measurement: h2=2h restructure (R15/R16, +58us), per-block
// re-stagger (R15), XSTEPS=256 (R15), forced phase alternation (R13),
// 2-CTA/SM (R10), batch-fused single stream (R9/R11), K-split (R8).
//
// Per chain: thread w in [0,128): p = w&1, u = w>>1, rows rA = p*64+u (i/f),
// rB = rA+128 (g/o); weights register-resident (2 x 32 f32x2). Unified
// MUFU.TANH activations, shfl_xor(1) gate exchange, p==0 lanes update c and
// store h (double-buffered by step parity). ONE named barrier per step.
//
// Backward direction = ONE LSTM step on x[T-1] from zero state (scan[0] of
// the reversed sequence), fused as an epilogue with the final linear.
struct ChainSmem {
    float h[2][64];             // double-buffered hidden state
    float hb[64];               // backward h (epilogue)
    float xring[2][XSTEPS * 8]; // padded x ring, 2 blocks (contiguous)
    float pad[8];               // absorbs end-of-ring shadow over-read
};

__global__ void __launch_bounds__(256, 1)
bilstm_kernel(const float* __restrict__ x,      // [B,T,I]
              const float* __restrict__ Wih_f,  // [256,7]
              const float* __restrict__ Whh_f,  // [256,64]
              const float* __restrict__ bih_f,  // [256]
              const float* __restrict__ bhh_f,  // [256]
              const float* __restrict__ Wih_b,  // [256,7]
              const float* __restrict__ Whh_b,  // unused (h0 = 0 for single bwd step)
              const float* __restrict__ bih_b,  // [256]
              const float* __restrict__ bhh_b,  // [256]
              const float* __restrict__ Wlin,   // [3,128]
              const float* __restrict__ blin,   // [3]
              float* __restrict__ out)          // [B,3]
{
    __shared__ __align__(16) ChainSmem cs[2];

    const int tid   = threadIdx.x;
    const int chain = tid >> 7;          // 0 or 1
    const int w     = tid & 127;         // within-chain thread id
    const int p     = w & 1;             // gate pair selector
    const int u     = w >> 1;            // hidden unit
    const int rA    = p * 64 + u;        // gate i (p=0) / f (p=1)
    const int rB    = rA + 128;          // gate g (p=0) / o (p=1)
    const int b     = blockIdx.x * 2 + chain;
    const int barid = 1 + chain;
    ChainSmem& S = cs[chain];

    const float* xb = x + (size_t)b * T_SEQ * INP;

    const uint32_t ring0 = (uint32_t)__cvta_generic_to_shared(&S.xring[0][0]);
    const uint32_t ring1 = (uint32_t)__cvta_generic_to_shared(&S.xring[1][0]);

    // activation of row B: tanh for p=0 (gate g), sigmoid for p=1 (gate o)
    const float actB_s = (p == 0) ? 1.0f : 0.5f;   // folded into weights
    const float actB_m = (p == 0) ? 1.0f : 0.5f;
    const float actB_b = (p == 0) ? 0.0f : 0.5f;

    // ---- weights into registers, with activation scales FOLDED IN ----
    // row A (i or f) is always sigmoid: scale 0.5. row B: actB_s.
    ull wA[32], wB[32];
    {
        const ull halfs = pack2(0.5f, 0.5f);
        const ull sB2   = pack2(actB_s, actB_s);
        const ull* a  = reinterpret_cast<const ull*>(Whh_f + rA * HID);
        const ull* c2 = reinterpret_cast<const ull*>(Whh_f + rB * HID);
#pragma unroll
        for (int m = 0; m < 32; m++) wA[m] = mul2(a[m], halfs);
#pragma unroll
        for (int m = 0; m < 32; m++) wB[m] = mul2(c2[m], sB2);
    }
    ull wihA[4], wihB[4];
    {
        float t[8];
#pragma unroll
        for (int i = 0; i < INP; i++) t[i] = 0.5f * Wih_f[rA * INP + i];
        t[7] = 0.0f;
#pragma unroll
        for (int m = 0; m < 4; m++) wihA[m] = pack2(t[2 * m], t[2 * m + 1]);
#pragma unroll
        for (int i = 0; i < INP; i++) t[i] = actB_s * Wih_f[rB * INP + i];
        t[7] = 0.0f;
#pragma unroll
        for (int m = 0; m < 4; m++) wihB[m] = pack2(t[2 * m], t[2 * m + 1]);
    }
    const ull biasA2 = pack2(0.5f   * (bih_f[rA] + bhh_f[rA]), 0.0f);
    const ull biasB2 = pack2(actB_s * (bih_f[rB] + bhh_f[rB]), 0.0f);

    // ---- init: h=0, zero ring pads, prefetch blocks 0 and 1 ----
    // thread w owns ring slot w (both buffers)
    if (w < 64) S.h[0][w] = 0.0f;
    S.xring[0][w * 8 + 7] = 0.0f;
    S.xring[1][w * 8 + 7] = 0.0f;
#pragma unroll
    for (int k = 0; k < 7; k++)
        cpa4(ring0 + (uint32_t)(w * 8 + k) * 4, xb + w * INP + k);
    cp_commit();
#pragma unroll
    for (int k = 0; k < 7; k++)
        cpa4(ring1 + (uint32_t)(w * 8 + k) * 4, xb + XBLK_FLOATS + w * INP + k);
    cp_commit();
    cp_wait0();
    float c = 0.0f;
    __syncthreads();

    // ---- one-time stagger: chain 1 burns ~300 cycles (anti-phase seed) ----
    if (chain == 1) {
        float d = actB_b + 1.5f;
#pragma unroll
        for (int i = 0; i < 75; i++) d = fmaf(d, 0.9999999f, 1e-9f);
        asm volatile("" :: "f"(d));
    }

    // xz for slot 0; xnext walks the contiguous ring (buf0 then buf1)
    ull xzA0, xzA1, xzB0, xzB1;
    const float* xnext = &S.xring[0][0];
    {
        ulonglong2 xv = *reinterpret_cast<const ulonglong2*>(xnext);
        ulonglong2 xw = *reinterpret_cast<const ulonglong2*>(xnext + 4);
        xzA0 = fma2(wihA[0], xv.x, biasA2);
        xzA1 = fma2(wihA[1], xv.y, 0ull);
        xzB0 = fma2(wihB[0], xv.x, biasB2);
        xzB1 = fma2(wihB[1], xv.y, 0ull);
        xzA0 = fma2(wihA[2], xw.x, xzA0);
        xzA1 = fma2(wihA[3], xw.y, xzA1);
        xzB0 = fma2(wihB[2], xw.x, xzB0);
        xzB1 = fma2(wihB[3], xw.y, xzB1);
        xnext += 8;
    }

    for (int blk = 0; blk < NBLK; blk++) {
        if (blk) {
            cp_wait0();   // ring block committed at the previous boundary landed
            asm volatile("bar.sync %0, 128;" :: "r"(barid) : "memory");
            int nb = blk + 1;
            if (nb < NBLK) {
                uint32_t dst = (nb & 1) ? ring1 : ring0;
                const float* src = xb + (size_t)nb * XBLK_FLOATS + w * INP;
#pragma unroll
                for (int k = 0; k < 7; k++)
                    cpa4(dst + (uint32_t)(w * 8 + k) * 4, src + k);
            }
            cp_commit();
            // recompute xz for slot t=blk*XSTEPS (the pre-boundary shadow may
            // have read unlanded data) and reset the walk
            const float* xc = &S.xring[blk & 1][0];
            ulonglong2 xv = *reinterpret_cast<const ulonglong2*>(xc);
            ulonglong2 xw = *reinterpret_cast<const ulonglong2*>(xc + 4);
            xzA0 = fma2(wihA[0], xv.x, biasA2);
            xzA1 = fma2(wihA[1], xv.y, 0ull);
            xzB0 = fma2(wihB[0], xv.x, biasB2);
            xzB1 = fma2(wihB[1], xv.y, 0ull);
            xzA0 = fma2(wihA[2], xw.x, xzA0);
            xzA1 = fma2(wihA[3], xw.y, xzA1);
            xzB0 = fma2(wihB[2], xw.x, xzB0);
            xzB1 = fma2(wihB[3], xw.y, xzB1);
            xnext = xc + 8;
        }

#pragma unroll 2
        for (int i = 0; i < XSTEPS; i++) {
            const int par = i & 1;       // h-buffer parity (XSTEPS even)

            // ---- z = xz + W_hh·h : 8 accumulators, dep depth 32 cyc ----
            ull a0 = xzA0, a1 = xzA1, a2 = 0ull, a3 = 0ull;
            ull b0 = xzB0, b1 = xzB1, b2 = 0ull, b3 = 0ull;
            const ulonglong2* h2 = reinterpret_cast<const ulonglong2*>(S.h[par]);
#pragma unroll
            for (int m = 0; m < 8; m++) {
                ulonglong2 ha  = h2[2 * m];
                ulonglong2 hbv = h2[2 * m + 1];
                a0 = fma2(wA[4 * m + 0], ha.x,  a0);
                a1 = fma2(wA[4 * m + 1], ha.y,  a1);
                b0 = fma2(wB[4 * m + 0], ha.x,  b0);
                b1 = fma2(wB[4 * m + 1], ha.y,  b1);
                a2 = fma2(wA[4 * m + 2], hbv.x, a2);
                a3 = fma2(wA[4 * m + 3], hbv.y, a3);
                b2 = fma2(wB[4 * m + 2], hbv.x, b2);
                b3 = fma2(wB[4 * m + 3], hbv.y, b3);
            }
            float2 fa = unpack2(add2(add2(a0, a2), add2(a1, a3)));
            float2 fb = unpack2(add2(add2(b0, b2), add2(b1, b3)));
            float zA = fa.x + fa.y;
            float zB = fb.x + fb.y;

            // ---- tail: activations (scales pre-folded), exchange, update ----
            float aA = fmaf(0.5f,   htanh(zA), 0.5f);
            float aB = fmaf(actB_m, htanh(zB), actB_b);
            float oA = __shfl_xor_sync(0xFFFFFFFFu, aA, 1);
            float oB = __shfl_xor_sync(0xFFFFFFFFu, aB, 1);
            if (p == 0) {
                c = oA * c + aA * aB;                // c = f*c + i*g
                S.h[par ^ 1][u] = oB * htanh(c);     // h = o*tanh(c)
            }

            // ---- barrier: arrive immediately after the h-store ----
            asm volatile("bar.sync %0, 128;" :: "r"(barid) : "memory");

            // ---- xz shadow AFTER the bar (overlaps drain/release) ----
            {
                ulonglong2 xv = *reinterpret_cast<const ulonglong2*>(xnext);
                ulonglong2 xw = *reinterpret_cast<const ulonglong2*>(xnext + 4);
                xzA0 = fma2(wihA[0], xv.x, biasA2);
                xzA1 = fma2(wihA[1], xv.y, 0ull);
                xzB0 = fma2(wihB[0], xv.x, biasB2);
                xzB1 = fma2(wihB[1], xv.y, 0ull);
                xzA0 = fma2(wihA[2], xw.x, xzA0);
                xzA1 = fma2(wihA[3], xw.y, xzA1);
                xzB0 = fma2(wihB[2], xw.x, xzB0);
                xzB1 = fma2(wihB[3], xw.y, xzB1);
                xnext += 8;
            }
        }
    }

    // ---- backward direction: ONE step on x[T-1] from zero state ----
    {
        const float* xl = &S.xring[1][(XSTEPS - 1) * 8]; // t=2047 -> buf 1, slot 127
        float zbA = bih_b[rA] + bhh_b[rA];
        float zbB = bih_b[rB] + bhh_b[rB];
#pragma unroll
        for (int i = 0; i < INP; i++) {
            zbA += Wih_b[rA * INP + i] * xl[i];
            zbB += Wih_b[rB * INP + i] * xl[i];
        }
        float aA = fmaf(0.5f, htanh(0.5f * zbA), 0.5f);
        float aB = fmaf(actB_m, htanh(actB_s * zbB), actB_b);
        float oB = __shfl_xor_sync(0xFFFFFFFFu, aB, 1);   // o
        if (p == 0) {
            S.hb[u] = oB * htanh(aA * aB);       // f*c0 == 0
        }
        asm volatile("bar.sync %0, 128;" :: "r"(barid) : "memory");
    }

    // ---- final linear: out[b] = W_lin @ concat(h_f, h_b) + b_lin ----
    // final forward h is in S.h[0] (last step has par=1, writes buffer 0)
    if (w < 3) {
        float a = blin[w];
#pragma unroll 16
        for (int k = 0; k < 64; k++) a += Wlin[w * 128 + k] * S.h[0][k];
#pragma unroll 16
        for (int k = 0; k < 64; k++) a += Wlin[w * 128 + 64 + k] * S.hb[k];
        out[b * 3 + w] = a;
    }
}

extern "C" void kernel_launch(void* const* d_in, const int* in_sizes, int n_in,
                              void* d_out, int out_size) {
    (void)in_sizes; (void)n_in; (void)out_size;
    bilstm_kernel<<<BATCH / 2, 256>>>(
        (const float*)d_in[0],  (const float*)d_in[1], (const float*)d_in[2],
        (const float*)d_in[3],  (const float*)d_in[4], (const float*)d_in[5],
        (const float*)d_in[6],  (const float*)d_in[7], (const float*)d_in[8],
        (const float*)d_in[9],  (const float*)d_in[10], (float*)d_out);
}